// round 3
// baseline (speedup 1.0000x reference)
#include <cuda_runtime.h>
#include <cuda_bf16.h>
#include <cstdint>

#define LRELU_ALPHA 0.2f
#define EXP_CLAMP 1000000.0f
#define DENOM_EPS 1e-10f
#define N_NODES 50000
#define N_EDGES 1600000
#define IN_F 128
#define OUT_F 64

// Device scratch (no allocation allowed in kernel_launch)
__device__ float g_Wh[N_NODES * OUT_F];
__device__ float g_s[N_NODES];
__device__ float g_t[N_NODES];
__device__ float g_denom[N_NODES];
__device__ int   g_adj64;   // 1 if adj is int64, 0 if int32

// ---------------------------------------------------------------------------
// Kernel 0: detect adj dtype. Edge indices < 50000 < 2^31, so for int64
// (little-endian) every odd 32-bit word is a zero high-word. For int32 the
// odd words are src indices (random in [0,50000)) — OR over 4096 of them is
// nonzero with overwhelming probability.
// ---------------------------------------------------------------------------
__global__ void detect_kernel(const unsigned int* __restrict__ adj_raw) {
    unsigned int acc = 0;
    int lane = threadIdx.x;                // one warp
    for (int i = 1 + 2 * lane; i < 8192; i += 64)
        acc |= adj_raw[i];
    #pragma unroll
    for (int o = 16; o > 0; o >>= 1)
        acc |= __shfl_down_sync(0xffffffffu, acc, o);
    if (lane == 0) g_adj64 = (acc == 0) ? 1 : 0;
}

__device__ __forceinline__ void load_edge(const void* __restrict__ adj, int i,
                                          int& dst, int& src) {
    if (g_adj64) {
        const longlong2* p = (const longlong2*)adj;
        longlong2 v = __ldg(p + i);
        dst = (int)v.x; src = (int)v.y;
    } else {
        const int2* p = (const int2*)adj;
        int2 v = __ldg(p + i);
        dst = v.x; src = v.y;
    }
}

// ---------------------------------------------------------------------------
// Kernel 1: init output to 0, denom to eps
// ---------------------------------------------------------------------------
__global__ void init_kernel(float* __restrict__ out) {
    int i = blockIdx.x * blockDim.x + threadIdx.x;
    int total = N_NODES * OUT_F;
    if (i < total) out[i] = 0.0f;
    if (i < N_NODES) g_denom[i] = DENOM_EPS;
}

// ---------------------------------------------------------------------------
// Kernel 2: Wh = h @ W   (h: [N,128], W: [128,64])
// blockDim = 256: 4 rows per iteration, col = tid & 63
// ---------------------------------------------------------------------------
__global__ void gemm_kernel(const float* __restrict__ h, const float* __restrict__ W) {
    __shared__ float Ws[IN_F * OUT_F];   // 32 KB
    for (int i = threadIdx.x; i < IN_F * OUT_F; i += blockDim.x)
        Ws[i] = W[i];
    __syncthreads();

    int col  = threadIdx.x & 63;
    int rgrp = threadIdx.x >> 6;          // 0..3

    for (int row = blockIdx.x * 4 + rgrp; row < N_NODES; row += gridDim.x * 4) {
        const float* hr = h + (size_t)row * IN_F;
        float acc = 0.0f;
        #pragma unroll 8
        for (int k = 0; k < IN_F; k++)
            acc = fmaf(hr[k], Ws[k * OUT_F + col], acc);
        g_Wh[(size_t)row * OUT_F + col] = acc;
    }
}

// ---------------------------------------------------------------------------
// Kernel 3: s = Wh @ a1, t = Wh @ a2  — one warp per row
// ---------------------------------------------------------------------------
__global__ void st_kernel(const float* __restrict__ a) {
    int gid  = blockIdx.x * blockDim.x + threadIdx.x;
    int row  = gid >> 5;
    int lane = threadIdx.x & 31;
    if (row >= N_NODES) return;

    float2 w = ((const float2*)(g_Wh + (size_t)row * OUT_F))[lane];
    float a1x = a[lane * 2],          a1y = a[lane * 2 + 1];
    float a2x = a[OUT_F + lane * 2],  a2y = a[OUT_F + lane * 2 + 1];
    float sv = w.x * a1x + w.y * a1y;
    float tv = w.x * a2x + w.y * a2y;
    #pragma unroll
    for (int o = 16; o > 0; o >>= 1) {
        sv += __shfl_down_sync(0xffffffffu, sv, o);
        tv += __shfl_down_sync(0xffffffffu, tv, o);
    }
    if (lane == 0) { g_s[row] = sv; g_t[row] = tv; }
}

// ---------------------------------------------------------------------------
// Kernel 4: denom[dst] += clamp(exp(lrelu(s[dst]+t[src])))
// ---------------------------------------------------------------------------
__global__ void denom_kernel(const void* __restrict__ adj) {
    int i = blockIdx.x * blockDim.x + threadIdx.x;
    if (i >= N_EDGES) return;
    int dst, src;
    load_edge(adj, i, dst, src);
    float e = g_s[dst] + g_t[src];
    e = (e > 0.0f) ? e : LRELU_ALPHA * e;
    float x = fminf(__expf(e), EXP_CLAMP);
    atomicAdd(g_denom + dst, x);
}

// ---------------------------------------------------------------------------
// Kernel 4b: invert denominator once per node (hoists FDIV out of scatter)
// ---------------------------------------------------------------------------
__global__ void recip_kernel() {
    int i = blockIdx.x * blockDim.x + threadIdx.x;
    if (i < N_NODES) g_denom[i] = __frcp_rn(g_denom[i]);
}

// ---------------------------------------------------------------------------
// Kernel 5: scatter — out[dst] += Wh[src] * att.
// 16 lanes per edge, each lane handles 4 consecutive floats (float4).
// Lanes 0/16 of each warp compute att + indices; shfl-broadcast to the group.
// Vector reduction via red.global.add.v4.f32 (sm_90+).
// ---------------------------------------------------------------------------
__global__ void scatter_kernel(const void* __restrict__ adj, float* __restrict__ out) {
    int gid   = blockIdx.x * blockDim.x + threadIdx.x;
    int lane  = threadIdx.x & 31;
    int edge  = gid >> 4;
    int chunk = lane & 15;
    bool valid = (edge < N_EDGES);
    int eidx = valid ? edge : (N_EDGES - 1);

    int dst = 0, src = 0;
    float att = 0.0f;
    if (chunk == 0) {
        load_edge(adj, eidx, dst, src);
        float e = g_s[dst] + g_t[src];
        e = (e > 0.0f) ? e : LRELU_ALPHA * e;
        float x = fminf(__expf(e), EXP_CLAMP);
        att = x * g_denom[dst];          // g_denom holds reciprocal now
    }
    int leader = lane & 16;
    dst = __shfl_sync(0xffffffffu, dst, leader);
    src = __shfl_sync(0xffffffffu, src, leader);
    att = __shfl_sync(0xffffffffu, att, leader);

    float4 w = ((const float4*)(g_Wh + (size_t)src * OUT_F))[chunk];
    float4 v;
    v.x = w.x * att; v.y = w.y * att; v.z = w.z * att; v.w = w.w * att;

    if (valid) {
        float* p = out + (size_t)dst * OUT_F + chunk * 4;
        asm volatile("red.global.add.v4.f32 [%0], {%1, %2, %3, %4};"
                     :: "l"(p), "f"(v.x), "f"(v.y), "f"(v.z), "f"(v.w)
                     : "memory");
    }
}

// ---------------------------------------------------------------------------
// Kernel 6: ELU in-place
// ---------------------------------------------------------------------------
__global__ void elu_kernel(float* __restrict__ out) {
    int i = blockIdx.x * blockDim.x + threadIdx.x;
    int total = N_NODES * OUT_F;
    if (i >= total) return;
    float v = out[i];
    out[i] = (v > 0.0f) ? v : expm1f(v);
}

// ---------------------------------------------------------------------------
extern "C" void kernel_launch(void* const* d_in, const int* in_sizes, int n_in,
                              void* d_out, int out_size) {
    const float* h   = (const float*)d_in[0];   // [50000, 128]
    const float* W   = (const float*)d_in[1];   // [128, 64]
    const float* a   = (const float*)d_in[2];   // [128, 1]
    const void*  adj = d_in[3];                 // [1.6M, 2] int32 or int64
    float* out = (float*)d_out;                 // [50000, 64]

    const int T = 256;

    // detect adj dtype
    detect_kernel<<<1, 32>>>((const unsigned int*)adj);
    // init out + denom
    {
        int total = N_NODES * OUT_F;
        init_kernel<<<(total + T - 1) / T, T>>>(out);
    }
    // Wh = h @ W
    gemm_kernel<<<592, T>>>(h, W);
    // s, t projections
    {
        int threads = N_NODES * 32;
        st_kernel<<<(threads + T - 1) / T, T>>>(a);
    }
    // denominator accumulation
    denom_kernel<<<(N_EDGES + T - 1) / T, T>>>(adj);
    // invert denominators
    recip_kernel<<<(N_NODES + T - 1) / T, T>>>();
    // edge scatter
    {
        long long threads = (long long)N_EDGES * 16;
        int blocks = (int)((threads + T - 1) / T);
        scatter_kernel<<<blocks, T>>>(adj, out);
    }
    // ELU
    {
        int total = N_NODES * OUT_F;
        elu_kernel<<<(total + T - 1) / T, T>>>(out);
    }
}

// round 4
// speedup vs baseline: 1.4394x; 1.4394x over previous
#include <cuda_runtime.h>
#include <cuda_bf16.h>
#include <cstdint>

#define LRELU_ALPHA 0.2f
#define EXP_CLAMP 1000000.0f
#define DENOM_EPS 1e-10f
#define N_NODES 50000
#define N_EDGES 1600000
#define IN_F 128
#define OUT_F 64

// Device scratch (no allocation allowed in kernel_launch)
__device__ float g_Wh[N_NODES * OUT_F];
__device__ float g_s[N_NODES];
__device__ float g_t[N_NODES];
__device__ float g_denom[N_NODES];
__device__ int   g_adj64;   // 1 if adj is int64, 0 if int32

// ---------------------------------------------------------------------------
// Kernel 0: detect adj dtype. Edge indices < 50000 < 2^31, so for int64
// (little-endian) every odd 32-bit word is a zero high-word.
// ---------------------------------------------------------------------------
__global__ void detect_kernel(const unsigned int* __restrict__ adj_raw) {
    unsigned int acc = 0;
    int lane = threadIdx.x;                // one warp
    for (int i = 1 + 2 * lane; i < 8192; i += 64)
        acc |= adj_raw[i];
    #pragma unroll
    for (int o = 16; o > 0; o >>= 1)
        acc |= __shfl_down_sync(0xffffffffu, acc, o);
    if (lane == 0) g_adj64 = (acc == 0) ? 1 : 0;
}

__device__ __forceinline__ void load_edge(const void* __restrict__ adj, int i,
                                          int& dst, int& src) {
    if (g_adj64) {
        const longlong2* p = (const longlong2*)adj;
        longlong2 v = __ldg(p + i);
        dst = (int)v.x; src = (int)v.y;
    } else {
        const int2* p = (const int2*)adj;
        int2 v = __ldg(p + i);
        dst = v.x; src = v.y;
    }
}

// ---------------------------------------------------------------------------
// Kernels 1+2: zero output (split in two so the edge kernel lands at ncu
// launch index 5 for profiling)
// ---------------------------------------------------------------------------
__global__ void zero_lo_kernel(float* __restrict__ out) {
    int i = blockIdx.x * blockDim.x + threadIdx.x;
    if (i < N_NODES * OUT_F / 2) ((float2*)out)[i] = make_float2(0.f, 0.f);
}
__global__ void zero_hi_kernel(float* __restrict__ out) {
    int i = blockIdx.x * blockDim.x + threadIdx.x;
    int half = N_NODES * OUT_F / 2;
    if (i < half) ((float2*)out)[i + half / 2] = make_float2(0.f, 0.f);
}

// ---------------------------------------------------------------------------
// Kernel 4: init denom to eps
// ---------------------------------------------------------------------------
__global__ void init_denom_kernel() {
    int i = blockIdx.x * blockDim.x + threadIdx.x;
    if (i < N_NODES) g_denom[i] = DENOM_EPS;
}

// ---------------------------------------------------------------------------
// Kernel 3: Wh = h @ W  with fused s/t projection epilogue.
// 16 threads per row, 4 cols (one float4) per thread. blockDim=256 -> 16 rows.
// ---------------------------------------------------------------------------
__global__ void gemm_kernel(const float* __restrict__ h, const float* __restrict__ W,
                            const float* __restrict__ a) {
    __shared__ float4 Ws[IN_F * (OUT_F / 4)];   // 128 x 16 float4 = 32 KB
    for (int i = threadIdx.x; i < IN_F * OUT_F / 4; i += blockDim.x)
        Ws[i] = ((const float4*)W)[i];
    __syncthreads();

    int c4   = threadIdx.x & 15;          // which float4 column group
    int rloc = threadIdx.x >> 4;          // 0..15
    int row  = blockIdx.x * 16 + rloc;
    if (row >= N_NODES) return;

    const float4* hr = (const float4*)(h + (size_t)row * IN_F);
    float4 acc = make_float4(0.f, 0.f, 0.f, 0.f);
    #pragma unroll 8
    for (int k4 = 0; k4 < IN_F / 4; k4++) {
        float4 hv = hr[k4];
        float4 w0 = Ws[(k4 * 4 + 0) * 16 + c4];
        float4 w1 = Ws[(k4 * 4 + 1) * 16 + c4];
        float4 w2 = Ws[(k4 * 4 + 2) * 16 + c4];
        float4 w3 = Ws[(k4 * 4 + 3) * 16 + c4];
        acc.x = fmaf(hv.x, w0.x, acc.x); acc.y = fmaf(hv.x, w0.y, acc.y);
        acc.z = fmaf(hv.x, w0.z, acc.z); acc.w = fmaf(hv.x, w0.w, acc.w);
        acc.x = fmaf(hv.y, w1.x, acc.x); acc.y = fmaf(hv.y, w1.y, acc.y);
        acc.z = fmaf(hv.y, w1.z, acc.z); acc.w = fmaf(hv.y, w1.w, acc.w);
        acc.x = fmaf(hv.z, w2.x, acc.x); acc.y = fmaf(hv.z, w2.y, acc.y);
        acc.z = fmaf(hv.z, w2.z, acc.z); acc.w = fmaf(hv.z, w2.w, acc.w);
        acc.x = fmaf(hv.w, w3.x, acc.x); acc.y = fmaf(hv.w, w3.y, acc.y);
        acc.z = fmaf(hv.w, w3.z, acc.z); acc.w = fmaf(hv.w, w3.w, acc.w);
    }
    ((float4*)(g_Wh + (size_t)row * OUT_F))[c4] = acc;

    // Fused s/t projection: s=Wh.a1, t=Wh.a2, reduce across the 16 lanes
    float4 a1 = ((const float4*)a)[c4];
    float4 a2 = ((const float4*)(a + OUT_F))[c4];
    float sv = acc.x * a1.x + acc.y * a1.y + acc.z * a1.z + acc.w * a1.w;
    float tv = acc.x * a2.x + acc.y * a2.y + acc.z * a2.z + acc.w * a2.w;
    #pragma unroll
    for (int o = 8; o > 0; o >>= 1) {
        sv += __shfl_down_sync(0xffffffffu, sv, o, 16);
        tv += __shfl_down_sync(0xffffffffu, tv, o, 16);
    }
    if (c4 == 0) { g_s[row] = sv; g_t[row] = tv; }
}

// ---------------------------------------------------------------------------
// Kernel 5 (the hot one): single fused edge pass.
// Leader lanes (chunk==0) compute x_exp, accumulate denom atomically, and
// broadcast; all 16 lanes red the UNNORMALIZED x_exp*Wh[src] into out[dst].
// Normalization is deferred to the final kernel (linearity of the sum).
// ---------------------------------------------------------------------------
__global__ void edge_kernel(const void* __restrict__ adj, float* __restrict__ out) {
    int gid   = blockIdx.x * blockDim.x + threadIdx.x;
    int lane  = threadIdx.x & 31;
    int edge  = gid >> 4;
    int chunk = lane & 15;
    bool valid = (edge < N_EDGES);
    int eidx = valid ? edge : (N_EDGES - 1);

    int dst = 0, src = 0;
    float x = 0.0f;
    if (chunk == 0) {
        load_edge(adj, eidx, dst, src);
        float e = g_s[dst] + g_t[src];
        e = (e > 0.0f) ? e : LRELU_ALPHA * e;
        x = fminf(__expf(e), EXP_CLAMP);
        if (valid) atomicAdd(g_denom + dst, x);
    }
    int leader = lane & 16;
    dst = __shfl_sync(0xffffffffu, dst, leader);
    src = __shfl_sync(0xffffffffu, src, leader);
    x   = __shfl_sync(0xffffffffu, x, leader);

    float4 w = ((const float4*)(g_Wh + (size_t)src * OUT_F))[chunk];
    float4 v;
    v.x = w.x * x; v.y = w.y * x; v.z = w.z * x; v.w = w.w * x;

    if (valid) {
        float* p = out + (size_t)dst * OUT_F + chunk * 4;
        asm volatile("red.global.add.v4.f32 [%0], {%1, %2, %3, %4};"
                     :: "l"(p), "f"(v.x), "f"(v.y), "f"(v.z), "f"(v.w)
                     : "memory");
    }
}

// ---------------------------------------------------------------------------
// Kernel 6: normalize by denom + ELU, in-place
// ---------------------------------------------------------------------------
__global__ void final_kernel(float* __restrict__ out) {
    int i = blockIdx.x * blockDim.x + threadIdx.x;
    int total = N_NODES * OUT_F;
    if (i >= total) return;
    float d = g_denom[i >> 6];            // broadcast within each 64-group
    float v = out[i] * __frcp_rn(d);
    out[i] = (v > 0.0f) ? v : expm1f(v);
}

// ---------------------------------------------------------------------------
extern "C" void kernel_launch(void* const* d_in, const int* in_sizes, int n_in,
                              void* d_out, int out_size) {
    const float* h   = (const float*)d_in[0];   // [50000, 128]
    const float* W   = (const float*)d_in[1];   // [128, 64]
    const float* a   = (const float*)d_in[2];   // [128, 1]
    const void*  adj = d_in[3];                 // [1.6M, 2] int32 or int64
    float* out = (float*)d_out;                 // [50000, 64]

    const int T = 256;
    int halfv2 = N_NODES * OUT_F / 4;           // float2 count per half

    detect_kernel<<<1, 32>>>((const unsigned int*)adj);                // idx 0
    zero_lo_kernel<<<(halfv2 + T - 1) / T, T>>>(out);                  // idx 1
    zero_hi_kernel<<<(halfv2 + T - 1) / T, T>>>(out);                  // idx 2
    gemm_kernel<<<(N_NODES + 15) / 16, T>>>(h, W, a);                  // idx 3
    init_denom_kernel<<<(N_NODES + T - 1) / T, T>>>();                 // idx 4
    {                                                                  // idx 5
        long long threads = (long long)N_EDGES * 16;
        int blocks = (int)((threads + T - 1) / T);
        edge_kernel<<<blocks, T>>>(adj, out);
    }
    {                                                                  // idx 6
        int total = N_NODES * OUT_F;
        final_kernel<<<(total + T - 1) / T, T>>>(out);
    }
}

// round 5
// speedup vs baseline: 1.8701x; 1.2993x over previous
#include <cuda_runtime.h>
#include <cuda_bf16.h>
#include <cstdint>

#define LRELU_ALPHA 0.2f
#define EXP_CLAMP 1000000.0f
#define DENOM_EPS 1e-10f
#define N_NODES 50000
#define N_EDGES 1600000
#define IN_F 128
#define OUT_F 64

#define TILE_R 128
#define KC 32
#define HS_PAD 132      // floats per transposed k-row (mult of 4, conflict-free reads)
#define WS_PAD 68       // floats per W k-row
#define GEMM_SMEM ((KC * HS_PAD + IN_F * WS_PAD) * 4)

// Device scratch (no allocation allowed in kernel_launch)
__device__ float g_Wh[N_NODES * OUT_F];
__device__ float g_s[N_NODES];
__device__ float g_t[N_NODES];
__device__ float g_denom[N_NODES];
__device__ int   g_adj64;   // 1 if adj is int64, 0 if int32

// Packed fp32x2 FMA (Blackwell sm_100+): d = a*b + c elementwise on pairs.
__device__ __forceinline__ float2 ffma2(float2 a, float2 b, float2 c) {
    float2 d;
    asm("fma.rn.f32x2 %0, %1, %2, %3;"
        : "=l"(*(unsigned long long*)&d)
        : "l"(*(unsigned long long*)&a),
          "l"(*(unsigned long long*)&b),
          "l"(*(unsigned long long*)&c));
    return d;
}

// ---------------------------------------------------------------------------
// Kernel 0: detect adj dtype (int64 -> odd 32-bit words are zero high-words)
// ---------------------------------------------------------------------------
__global__ void detect_kernel(const unsigned int* __restrict__ adj_raw) {
    unsigned int acc = 0;
    int lane = threadIdx.x;                // one warp
    for (int i = 1 + 2 * lane; i < 8192; i += 64)
        acc |= adj_raw[i];
    #pragma unroll
    for (int o = 16; o > 0; o >>= 1)
        acc |= __shfl_down_sync(0xffffffffu, acc, o);
    if (lane == 0) g_adj64 = (acc == 0) ? 1 : 0;
}

__device__ __forceinline__ void load_edge(const void* __restrict__ adj, int i,
                                          int& dst, int& src) {
    if (g_adj64) {
        const longlong2* p = (const longlong2*)adj;
        longlong2 v = __ldg(p + i);
        dst = (int)v.x; src = (int)v.y;
    } else {
        const int2* p = (const int2*)adj;
        int2 v = __ldg(p + i);
        dst = v.x; src = v.y;
    }
}

// ---------------------------------------------------------------------------
// GEMM: Wh = h @ W with fused s/t projection.
// Block: 256 threads -> tile 128 rows x 64 cols.
// Thread: 8 rows x 4 cols, accumulators packed as float2 over ROW pairs.
// ---------------------------------------------------------------------------
__global__ __launch_bounds__(256) void gemm_kernel(const float* __restrict__ h,
                                                   const float* __restrict__ W,
                                                   const float* __restrict__ a) {
    extern __shared__ float smem[];
    float* hs = smem;                         // [KC][HS_PAD] transposed h chunk
    float* Ws = smem + KC * HS_PAD;           // [IN_F][WS_PAD]

    int tid = threadIdx.x;

    // Load full W tile once (coalesced, conflict-free writes)
    for (int i = tid; i < IN_F * OUT_F; i += 256) {
        int k = i >> 6, c = i & 63;
        Ws[k * WS_PAD + c] = W[i];
    }

    int colg = tid & 15;          // 16 col groups x 4 cols
    int rowg = tid >> 4;          // 16 row groups x 8 rows
    int c0 = colg * 4;
    int r0 = rowg * 8;
    int R0 = blockIdx.x * TILE_R;

    float2 acc[4][4];             // [rowpair][col]
    #pragma unroll
    for (int p = 0; p < 4; p++)
        #pragma unroll
        for (int j = 0; j < 4; j++)
            acc[p][j] = make_float2(0.f, 0.f);

    for (int kc = 0; kc < IN_F; kc += KC) {
        __syncthreads();
        // Load h chunk transposed: hs[k][row] = h[R0+row][kc+k]
        #pragma unroll
        for (int it = 0; it < (TILE_R * KC / 4) / 256; it++) {
            int i   = tid + it * 256;       // [0, 1024)
            int row = i >> 3;
            int k4  = i & 7;
            int gr  = R0 + row;
            if (gr >= N_NODES) gr = 0;      // clamped read; stores guarded later
            float4 v = *(const float4*)(h + (size_t)gr * IN_F + kc + k4 * 4);
            hs[(k4 * 4 + 0) * HS_PAD + row] = v.x;
            hs[(k4 * 4 + 1) * HS_PAD + row] = v.y;
            hs[(k4 * 4 + 2) * HS_PAD + row] = v.z;
            hs[(k4 * 4 + 3) * HS_PAD + row] = v.w;
        }
        __syncthreads();

        #pragma unroll 8
        for (int k = 0; k < KC; k++) {
            float4 A = *(const float4*)(hs + k * HS_PAD + r0);      // rows r0..r0+3
            float4 B = *(const float4*)(hs + k * HS_PAD + r0 + 4);  // rows r0+4..r0+7
            float2 hp[4] = { make_float2(A.x, A.y), make_float2(A.z, A.w),
                             make_float2(B.x, B.y), make_float2(B.z, B.w) };
            float4 wv = *(const float4*)(Ws + (kc + k) * WS_PAD + c0);
            float2 w0 = make_float2(wv.x, wv.x);
            float2 w1 = make_float2(wv.y, wv.y);
            float2 w2 = make_float2(wv.z, wv.z);
            float2 w3 = make_float2(wv.w, wv.w);
            #pragma unroll
            for (int p = 0; p < 4; p++) {
                acc[p][0] = ffma2(hp[p], w0, acc[p][0]);
                acc[p][1] = ffma2(hp[p], w1, acc[p][1]);
                acc[p][2] = ffma2(hp[p], w2, acc[p][2]);
                acc[p][3] = ffma2(hp[p], w3, acc[p][3]);
            }
        }
    }

    // Store Wh (4 cols per row, 8 rows)
    #pragma unroll
    for (int p = 0; p < 4; p++) {
        int r = R0 + r0 + 2 * p;
        if (r < N_NODES) {
            float4 lo = make_float4(acc[p][0].x, acc[p][1].x, acc[p][2].x, acc[p][3].x);
            *(float4*)(g_Wh + (size_t)r * OUT_F + c0) = lo;
        }
        if (r + 1 < N_NODES) {
            float4 hi = make_float4(acc[p][0].y, acc[p][1].y, acc[p][2].y, acc[p][3].y);
            *(float4*)(g_Wh + (size_t)(r + 1) * OUT_F + c0) = hi;
        }
    }

    // Fused s/t projection: reduce partial dot over the 16 col-groups
    float2 sp[4], tp[4];
    #pragma unroll
    for (int p = 0; p < 4; p++) { sp[p] = make_float2(0.f, 0.f); tp[p] = make_float2(0.f, 0.f); }
    #pragma unroll
    for (int j = 0; j < 4; j++) {
        float a1v = a[c0 + j];
        float a2v = a[OUT_F + c0 + j];
        float2 a1d = make_float2(a1v, a1v);
        float2 a2d = make_float2(a2v, a2v);
        #pragma unroll
        for (int p = 0; p < 4; p++) {
            sp[p] = ffma2(acc[p][j], a1d, sp[p]);
            tp[p] = ffma2(acc[p][j], a2d, tp[p]);
        }
    }
    #pragma unroll
    for (int o = 8; o > 0; o >>= 1) {
        #pragma unroll
        for (int p = 0; p < 4; p++) {
            sp[p].x += __shfl_down_sync(0xffffffffu, sp[p].x, o, 16);
            sp[p].y += __shfl_down_sync(0xffffffffu, sp[p].y, o, 16);
            tp[p].x += __shfl_down_sync(0xffffffffu, tp[p].x, o, 16);
            tp[p].y += __shfl_down_sync(0xffffffffu, tp[p].y, o, 16);
        }
    }
    if (colg == 0) {
        #pragma unroll
        for (int p = 0; p < 4; p++) {
            int r = R0 + r0 + 2 * p;
            if (r < N_NODES)     { g_s[r]     = sp[p].x; g_t[r]     = tp[p].x; }
            if (r + 1 < N_NODES) { g_s[r + 1] = sp[p].y; g_t[r + 1] = tp[p].y; }
        }
    }
}

// ---------------------------------------------------------------------------
// Init: zero out, denom = eps
// ---------------------------------------------------------------------------
__global__ void init_all_kernel(float* __restrict__ out) {
    int i = blockIdx.x * blockDim.x + threadIdx.x;
    if (i < N_NODES * OUT_F / 4)
        ((float4*)out)[i] = make_float4(0.f, 0.f, 0.f, 0.f);
    if (i < N_NODES) g_denom[i] = DENOM_EPS;
}

// ---------------------------------------------------------------------------
// Edge pass (hot): leaders compute x_exp + denom atomics; all 16 lanes
// red the UNNORMALIZED x_exp*Wh[src] into out[dst]. Normalize later.
// ---------------------------------------------------------------------------
__global__ void edge_kernel(const void* __restrict__ adj, float* __restrict__ out) {
    int gid   = blockIdx.x * blockDim.x + threadIdx.x;
    int lane  = threadIdx.x & 31;
    int edge  = gid >> 4;
    int chunk = lane & 15;
    bool valid = (edge < N_EDGES);
    int eidx = valid ? edge : (N_EDGES - 1);

    int dst = 0, src = 0;
    float x = 0.0f;
    if (chunk == 0) {
        load_edge(adj, eidx, dst, src);
        float e = g_s[dst] + g_t[src];
        e = (e > 0.0f) ? e : LRELU_ALPHA * e;
        x = fminf(__expf(e), EXP_CLAMP);
        if (valid) atomicAdd(g_denom + dst, x);
    }
    int leader = lane & 16;
    dst = __shfl_sync(0xffffffffu, dst, leader);
    src = __shfl_sync(0xffffffffu, src, leader);
    x   = __shfl_sync(0xffffffffu, x, leader);

    float4 w = ((const float4*)(g_Wh + (size_t)src * OUT_F))[chunk];
    float4 v;
    v.x = w.x * x; v.y = w.y * x; v.z = w.z * x; v.w = w.w * x;

    if (valid) {
        float* p = out + (size_t)dst * OUT_F + chunk * 4;
        asm volatile("red.global.add.v4.f32 [%0], {%1, %2, %3, %4};"
                     :: "l"(p), "f"(v.x), "f"(v.y), "f"(v.z), "f"(v.w)
                     : "memory");
    }
}

// ---------------------------------------------------------------------------
// Final: normalize by denom + ELU, in-place
// ---------------------------------------------------------------------------
__global__ void final_kernel(float* __restrict__ out) {
    int i = blockIdx.x * blockDim.x + threadIdx.x;
    int total = N_NODES * OUT_F;
    if (i >= total) return;
    float d = g_denom[i >> 6];
    float v = out[i] * __frcp_rn(d);
    out[i] = (v > 0.0f) ? v : expm1f(v);
}

// ---------------------------------------------------------------------------
extern "C" void kernel_launch(void* const* d_in, const int* in_sizes, int n_in,
                              void* d_out, int out_size) {
    const float* h   = (const float*)d_in[0];   // [50000, 128]
    const float* W   = (const float*)d_in[1];   // [128, 64]
    const float* a   = (const float*)d_in[2];   // [128, 1]
    const void*  adj = d_in[3];                 // [1.6M, 2] int32 or int64
    float* out = (float*)d_out;                 // [50000, 64]

    const int T = 256;

    static bool smem_set = false;
    if (!smem_set) {
        cudaFuncSetAttribute(gemm_kernel,
                             cudaFuncAttributeMaxDynamicSharedMemorySize, GEMM_SMEM);
        smem_set = true;
    }

    detect_kernel<<<1, 32>>>((const unsigned int*)adj);                     // idx 0
    gemm_kernel<<<(N_NODES + TILE_R - 1) / TILE_R, 256, GEMM_SMEM>>>(h, W, a); // idx 1
    {                                                                       // idx 2
        int n = N_NODES * OUT_F / 4;   // covers denom too (50000 < 800000)
        init_all_kernel<<<(n + T - 1) / T, T>>>(out);
    }
    {                                                                       // idx 3 (profiled)
        long long threads = (long long)N_EDGES * 16;
        int blocks = (int)((threads + T - 1) / T);
        edge_kernel<<<blocks, T>>>(adj, out);
    }
    {                                                                       // idx 4
        int total = N_NODES * OUT_F;
        final_kernel<<<(total + T - 1) / T, T>>>(out);
    }
}

// round 6
// speedup vs baseline: 2.6183x; 1.4001x over previous
#include <cuda_runtime.h>
#include <cuda_bf16.h>
#include <cstdint>

#define LRELU_ALPHA 0.2f
#define EXP_CLAMP 1000000.0f
#define DENOM_EPS 1e-10f
#define N_NODES 50000
#define N_EDGES 1600000
#define IN_F 128
#define OUT_F 64
#define CAP 128          // bucket capacity per dst (Poisson(32) max ~70)

#define TILE_R 128
#define KC 32
#define HS_PAD 132
#define WS_PAD 68
#define GEMM_SMEM ((KC * HS_PAD + IN_F * WS_PAD) * 4)

// Device scratch (no allocation allowed in kernel_launch)
__device__ float g_Wh[N_NODES * OUT_F];
__device__ float g_s[N_NODES];
__device__ float g_t[N_NODES];
__device__ float g_denom[N_NODES];
__device__ int   g_cnt[N_NODES];
__device__ int   g_bucket[N_NODES * CAP];   // 25.6 MB
__device__ int   g_adj64;

// Packed fp32x2 FMA (Blackwell sm_100+)
__device__ __forceinline__ float2 ffma2(float2 a, float2 b, float2 c) {
    float2 d;
    asm("fma.rn.f32x2 %0, %1, %2, %3;"
        : "=l"(*(unsigned long long*)&d)
        : "l"(*(unsigned long long*)&a),
          "l"(*(unsigned long long*)&b),
          "l"(*(unsigned long long*)&c));
    return d;
}

__device__ __forceinline__ void load_edge(const void* __restrict__ adj, int i,
                                          int& dst, int& src) {
    if (g_adj64) {
        const longlong2* p = (const longlong2*)adj;
        longlong2 v = __ldg(p + i);
        dst = (int)v.x; src = (int)v.y;
    } else {
        const int2* p = (const int2*)adj;
        int2 v = __ldg(p + i);
        dst = v.x; src = v.y;
    }
}

// ---------------------------------------------------------------------------
// Kernel 0: init (zero out, cnt; denom=eps) + fused adj dtype detection
// ---------------------------------------------------------------------------
__global__ void init_kernel(float* __restrict__ out, const unsigned int* __restrict__ adj_raw) {
    int i = blockIdx.x * blockDim.x + threadIdx.x;
    if (i < N_NODES * OUT_F / 4)
        ((float4*)out)[i] = make_float4(0.f, 0.f, 0.f, 0.f);
    if (i < N_NODES) { g_denom[i] = DENOM_EPS; g_cnt[i] = 0; }

    // adj dtype detect: block 0, warp 0. int64 => odd 32-bit words all zero.
    if (blockIdx.x == 0 && threadIdx.x < 32) {
        unsigned int acc = 0;
        for (int j = 1 + 2 * threadIdx.x; j < 8192; j += 64)
            acc |= adj_raw[j];
        #pragma unroll
        for (int o = 16; o > 0; o >>= 1)
            acc |= __shfl_down_sync(0xffffffffu, acc, o);
        if (threadIdx.x == 0) g_adj64 = (acc == 0) ? 1 : 0;
    }
}

// ---------------------------------------------------------------------------
// Kernel 1: GEMM Wh = h @ W with fused s/t projection (proven in R5)
// ---------------------------------------------------------------------------
__global__ __launch_bounds__(256) void gemm_kernel(const float* __restrict__ h,
                                                   const float* __restrict__ W,
                                                   const float* __restrict__ a) {
    extern __shared__ float smem[];
    float* hs = smem;                         // [KC][HS_PAD] transposed h chunk
    float* Ws = smem + KC * HS_PAD;           // [IN_F][WS_PAD]

    int tid = threadIdx.x;
    for (int i = tid; i < IN_F * OUT_F; i += 256) {
        int k = i >> 6, c = i & 63;
        Ws[k * WS_PAD + c] = W[i];
    }

    int colg = tid & 15;
    int rowg = tid >> 4;
    int c0 = colg * 4;
    int r0 = rowg * 8;
    int R0 = blockIdx.x * TILE_R;

    float2 acc[4][4];
    #pragma unroll
    for (int p = 0; p < 4; p++)
        #pragma unroll
        for (int j = 0; j < 4; j++)
            acc[p][j] = make_float2(0.f, 0.f);

    for (int kc = 0; kc < IN_F; kc += KC) {
        __syncthreads();
        #pragma unroll
        for (int it = 0; it < (TILE_R * KC / 4) / 256; it++) {
            int i   = tid + it * 256;
            int row = i >> 3;
            int k4  = i & 7;
            int gr  = R0 + row;
            if (gr >= N_NODES) gr = 0;
            float4 v = *(const float4*)(h + (size_t)gr * IN_F + kc + k4 * 4);
            hs[(k4 * 4 + 0) * HS_PAD + row] = v.x;
            hs[(k4 * 4 + 1) * HS_PAD + row] = v.y;
            hs[(k4 * 4 + 2) * HS_PAD + row] = v.z;
            hs[(k4 * 4 + 3) * HS_PAD + row] = v.w;
        }
        __syncthreads();

        #pragma unroll 8
        for (int k = 0; k < KC; k++) {
            float4 A = *(const float4*)(hs + k * HS_PAD + r0);
            float4 B = *(const float4*)(hs + k * HS_PAD + r0 + 4);
            float2 hp[4] = { make_float2(A.x, A.y), make_float2(A.z, A.w),
                             make_float2(B.x, B.y), make_float2(B.z, B.w) };
            float4 wv = *(const float4*)(Ws + (kc + k) * WS_PAD + c0);
            float2 w0 = make_float2(wv.x, wv.x);
            float2 w1 = make_float2(wv.y, wv.y);
            float2 w2 = make_float2(wv.z, wv.z);
            float2 w3 = make_float2(wv.w, wv.w);
            #pragma unroll
            for (int p = 0; p < 4; p++) {
                acc[p][0] = ffma2(hp[p], w0, acc[p][0]);
                acc[p][1] = ffma2(hp[p], w1, acc[p][1]);
                acc[p][2] = ffma2(hp[p], w2, acc[p][2]);
                acc[p][3] = ffma2(hp[p], w3, acc[p][3]);
            }
        }
    }

    #pragma unroll
    for (int p = 0; p < 4; p++) {
        int r = R0 + r0 + 2 * p;
        if (r < N_NODES) {
            float4 lo = make_float4(acc[p][0].x, acc[p][1].x, acc[p][2].x, acc[p][3].x);
            *(float4*)(g_Wh + (size_t)r * OUT_F + c0) = lo;
        }
        if (r + 1 < N_NODES) {
            float4 hi = make_float4(acc[p][0].y, acc[p][1].y, acc[p][2].y, acc[p][3].y);
            *(float4*)(g_Wh + (size_t)(r + 1) * OUT_F + c0) = hi;
        }
    }

    float2 sp[4], tp[4];
    #pragma unroll
    for (int p = 0; p < 4; p++) { sp[p] = make_float2(0.f, 0.f); tp[p] = make_float2(0.f, 0.f); }
    #pragma unroll
    for (int j = 0; j < 4; j++) {
        float a1v = a[c0 + j];
        float a2v = a[OUT_F + c0 + j];
        float2 a1d = make_float2(a1v, a1v);
        float2 a2d = make_float2(a2v, a2v);
        #pragma unroll
        for (int p = 0; p < 4; p++) {
            sp[p] = ffma2(acc[p][j], a1d, sp[p]);
            tp[p] = ffma2(acc[p][j], a2d, tp[p]);
        }
    }
    #pragma unroll
    for (int o = 8; o > 0; o >>= 1) {
        #pragma unroll
        for (int p = 0; p < 4; p++) {
            sp[p].x += __shfl_down_sync(0xffffffffu, sp[p].x, o, 16);
            sp[p].y += __shfl_down_sync(0xffffffffu, sp[p].y, o, 16);
            tp[p].x += __shfl_down_sync(0xffffffffu, tp[p].x, o, 16);
            tp[p].y += __shfl_down_sync(0xffffffffu, tp[p].y, o, 16);
        }
    }
    if (colg == 0) {
        #pragma unroll
        for (int p = 0; p < 4; p++) {
            int r = R0 + r0 + 2 * p;
            if (r < N_NODES)     { g_s[r]     = sp[p].x; g_t[r]     = tp[p].x; }
            if (r + 1 < N_NODES) { g_s[r + 1] = sp[p].y; g_t[r + 1] = tp[p].y; }
        }
    }
}

// ---------------------------------------------------------------------------
// Kernel 2: bucket scatter — bin src by dst. Overflow (never on this data):
// guaranteed-correct red fallback + denom atomic.
// ---------------------------------------------------------------------------
__global__ void scatter_kernel(const void* __restrict__ adj, float* __restrict__ out) {
    int i = blockIdx.x * blockDim.x + threadIdx.x;
    if (i >= N_EDGES) return;
    int dst, src;
    load_edge(adj, i, dst, src);
    int c = atomicAdd(g_cnt + dst, 1);
    if (c < CAP) {
        g_bucket[(size_t)dst * CAP + c] = src;
    } else {
        float e = g_s[dst] + g_t[src];
        e = (e > 0.0f) ? e : LRELU_ALPHA * e;
        float x = fminf(__expf(e), EXP_CLAMP);
        atomicAdd(g_denom + dst, x);
        const float* w = g_Wh + (size_t)src * OUT_F;
        float* o = out + (size_t)dst * OUT_F;
        for (int j = 0; j < OUT_F; j++)
            atomicAdd(o + j, x * w[j]);
    }
}

// ---------------------------------------------------------------------------
// Kernel 3 (hot, profiled): one warp per dst node.
// Lanes batch-compute 32 x_exp values, broadcast (src,x), accumulate
// sum(x * Wh[src]) in registers (float2 per lane). Normalize+ELU inline.
// ---------------------------------------------------------------------------
__global__ __launch_bounds__(256) void aggregate_kernel(float* __restrict__ out) {
    int warp = (blockIdx.x * blockDim.x + threadIdx.x) >> 5;
    int lane = threadIdx.x & 31;
    if (warp >= N_NODES) return;
    int d = warp;
    int n = g_cnt[d];
    bool ovf = (n > CAP);
    if (ovf) n = CAP;

    float sd = g_s[d];
    const int* bkt = g_bucket + (size_t)d * CAP;

    float2 acc = make_float2(0.f, 0.f);
    float xsum = 0.f;

    for (int base = 0; base < n; base += 32) {
        int i = base + lane;
        int src = 0;
        float x = 0.f;
        if (i < n) {
            src = __ldg(bkt + i);
            float e = sd + __ldg(g_t + src);
            e = (e > 0.0f) ? e : LRELU_ALPHA * e;
            x = fminf(__expf(e), EXP_CLAMP);
            xsum += x;
        }
        int m = n - base; if (m > 32) m = 32;
        #pragma unroll 4
        for (int j = 0; j < m; j++) {
            float xj = __shfl_sync(0xffffffffu, x, j);
            int   sj = __shfl_sync(0xffffffffu, src, j);
            float2 w = *(const float2*)(g_Wh + (size_t)sj * OUT_F + lane * 2);
            acc = ffma2(make_float2(xj, xj), w, acc);
        }
    }

    // warp-reduce xsum
    #pragma unroll
    for (int o = 16; o > 0; o >>= 1)
        xsum += __shfl_xor_sync(0xffffffffu, xsum, o);

    float2* po = (float2*)(out + (size_t)d * OUT_F) + lane;
    if (!ovf) {
        float r = __frcp_rn(xsum + DENOM_EPS);
        float vx = acc.x * r, vy = acc.y * r;
        vx = (vx > 0.0f) ? vx : expm1f(vx);
        vy = (vy > 0.0f) ? vy : expm1f(vy);
        *po = make_float2(vx, vy);
    } else {
        asm volatile("red.global.add.v2.f32 [%0], {%1, %2};"
                     :: "l"(po), "f"(acc.x), "f"(acc.y) : "memory");
        if (lane == 0) atomicAdd(g_denom + d, xsum);
    }
}

// ---------------------------------------------------------------------------
// Kernel 4: finalize ONLY overflowed nodes (normally none)
// ---------------------------------------------------------------------------
__global__ void final_kernel(float* __restrict__ out) {
    int i = blockIdx.x * blockDim.x + threadIdx.x;
    if (i >= N_NODES * OUT_F) return;
    int d = i >> 6;
    if (g_cnt[d] <= CAP) return;
    float v = out[i] * __frcp_rn(g_denom[d]);
    out[i] = (v > 0.0f) ? v : expm1f(v);
}

// ---------------------------------------------------------------------------
extern "C" void kernel_launch(void* const* d_in, const int* in_sizes, int n_in,
                              void* d_out, int out_size) {
    const float* h   = (const float*)d_in[0];   // [50000, 128]
    const float* W   = (const float*)d_in[1];   // [128, 64]
    const float* a   = (const float*)d_in[2];   // [128, 1]
    const void*  adj = d_in[3];                 // [1.6M, 2] int32 or int64
    float* out = (float*)d_out;                 // [50000, 64]

    const int T = 256;

    static bool smem_set = false;
    if (!smem_set) {
        cudaFuncSetAttribute(gemm_kernel,
                             cudaFuncAttributeMaxDynamicSharedMemorySize, GEMM_SMEM);
        smem_set = true;
    }

    {                                                                   // idx 0
        int n = N_NODES * OUT_F / 4;
        init_kernel<<<(n + T - 1) / T, T>>>(out, (const unsigned int*)adj);
    }
    gemm_kernel<<<(N_NODES + TILE_R - 1) / TILE_R, 256, GEMM_SMEM>>>(h, W, a); // idx 1
    scatter_kernel<<<(N_EDGES + T - 1) / T, T>>>(adj, out);             // idx 2
    {                                                                   // idx 3 (profiled)
        long long threads = (long long)N_NODES * 32;
        int blocks = (int)((threads + T - 1) / T);
        aggregate_kernel<<<blocks, T>>>(out);
    }
    {                                                                   // idx 4
        int total = N_NODES * OUT_F;
        final_kernel<<<(total + T - 1) / T, T>>>(out);
    }
}

// round 7
// speedup vs baseline: 2.8237x; 1.0784x over previous
#include <cuda_runtime.h>
#include <cuda_fp16.h>
#include <cstdint>

#define LRELU_ALPHA 0.2f
#define EXP_CLAMP 1000000.0f
#define DENOM_EPS 1e-10f
#define N_NODES 50000
#define N_EDGES 1600000
#define IN_F 128
#define OUT_F 64
#define CAP 128          // bucket capacity per dst (Poisson(32), max ~70)
#define OVF_MAX 32768

#define TILE_R 128
#define KC 32
#define HS_PAD 132
#define WS_PAD 68
#define GEMM_SMEM ((KC * HS_PAD + IN_F * WS_PAD) * 4)
#define GEMM_BLOCKS ((N_NODES + TILE_R - 1) / TILE_R)        // 391
#define SCAT_BLOCKS ((N_EDGES + 255) / 256)                  // 6250

// Device scratch (no allocation allowed in kernel_launch)
__device__ __half g_Whh[N_NODES * OUT_F];     // fp16 Wh (6.4 MB)
__device__ float g_s[N_NODES];
__device__ float g_t[N_NODES];
__device__ float g_denom[N_NODES];
__device__ int   g_cnt[N_NODES];
__device__ int   g_bucket[N_NODES * CAP];     // 25.6 MB
__device__ int   g_ovf_cnt;
__device__ int2  g_ovf[OVF_MAX];
__device__ int   g_adj64;

// Packed fp32x2 FMA (Blackwell sm_100+)
__device__ __forceinline__ float2 ffma2(float2 a, float2 b, float2 c) {
    float2 d;
    asm("fma.rn.f32x2 %0, %1, %2, %3;"
        : "=l"(*(unsigned long long*)&d)
        : "l"(*(unsigned long long*)&a),
          "l"(*(unsigned long long*)&b),
          "l"(*(unsigned long long*)&c));
    return d;
}

__device__ __forceinline__ void load_edge(const void* __restrict__ adj, int i,
                                          int& dst, int& src) {
    if (g_adj64) {
        const longlong2* p = (const longlong2*)adj;
        longlong2 v = __ldg(p + i);
        dst = (int)v.x; src = (int)v.y;
    } else {
        const int2* p = (const int2*)adj;
        int2 v = __ldg(p + i);
        dst = v.x; src = v.y;
    }
}

// ---------------------------------------------------------------------------
// Kernel 0: init (zero out/cnt/ovf_cnt, denom=eps) + fused adj dtype detect
// ---------------------------------------------------------------------------
__global__ void init_kernel(float* __restrict__ out, const unsigned int* __restrict__ adj_raw) {
    int i = blockIdx.x * blockDim.x + threadIdx.x;
    if (i < N_NODES * OUT_F / 4)
        ((float4*)out)[i] = make_float4(0.f, 0.f, 0.f, 0.f);
    if (i < N_NODES) { g_denom[i] = DENOM_EPS; g_cnt[i] = 0; }
    if (i == 0) g_ovf_cnt = 0;

    if (blockIdx.x == 0 && threadIdx.x < 32) {
        unsigned int acc = 0;
        for (int j = 1 + 2 * threadIdx.x; j < 8192; j += 64)
            acc |= adj_raw[j];
        #pragma unroll
        for (int o = 16; o > 0; o >>= 1)
            acc |= __shfl_down_sync(0xffffffffu, acc, o);
        if (threadIdx.x == 0) g_adj64 = (acc == 0) ? 1 : 0;
    }
}

// ---------------------------------------------------------------------------
// Kernel 1 (fused): blocks [0,391) do GEMM tile; blocks [391, 6641) do the
// bucket scatter. The two halves are fully independent.
// ---------------------------------------------------------------------------
__global__ __launch_bounds__(256) void gs_kernel(const float* __restrict__ h,
                                                 const float* __restrict__ W,
                                                 const float* __restrict__ a,
                                                 const void* __restrict__ adj) {
    if (blockIdx.x >= GEMM_BLOCKS) {
        // ---- scatter: bin src by dst; overflow goes to explicit list ----
        int i = (blockIdx.x - GEMM_BLOCKS) * 256 + threadIdx.x;
        if (i >= N_EDGES) return;
        int dst, src;
        load_edge(adj, i, dst, src);
        int c = atomicAdd(g_cnt + dst, 1);
        if (c < CAP) {
            g_bucket[(size_t)dst * CAP + c] = src;
        } else {
            int p = atomicAdd(&g_ovf_cnt, 1);
            if (p < OVF_MAX) g_ovf[p] = make_int2(dst, src);
        }
        return;
    }

    // ---- GEMM: Wh = h @ W (fp16 out) with fused s/t projection ----
    extern __shared__ float smem[];
    float* hs = smem;                         // [KC][HS_PAD] transposed h chunk
    float* Ws = smem + KC * HS_PAD;           // [IN_F][WS_PAD]

    int tid = threadIdx.x;
    for (int i = tid; i < IN_F * OUT_F; i += 256) {
        int k = i >> 6, c = i & 63;
        Ws[k * WS_PAD + c] = W[i];
    }

    int colg = tid & 15;
    int rowg = tid >> 4;
    int c0 = colg * 4;
    int r0 = rowg * 8;
    int R0 = blockIdx.x * TILE_R;

    float2 acc[4][4];
    #pragma unroll
    for (int p = 0; p < 4; p++)
        #pragma unroll
        for (int j = 0; j < 4; j++)
            acc[p][j] = make_float2(0.f, 0.f);

    for (int kc = 0; kc < IN_F; kc += KC) {
        __syncthreads();
        #pragma unroll
        for (int it = 0; it < (TILE_R * KC / 4) / 256; it++) {
            int i   = tid + it * 256;
            int row = i >> 3;
            int k4  = i & 7;
            int gr  = R0 + row;
            if (gr >= N_NODES) gr = 0;
            float4 v = *(const float4*)(h + (size_t)gr * IN_F + kc + k4 * 4);
            hs[(k4 * 4 + 0) * HS_PAD + row] = v.x;
            hs[(k4 * 4 + 1) * HS_PAD + row] = v.y;
            hs[(k4 * 4 + 2) * HS_PAD + row] = v.z;
            hs[(k4 * 4 + 3) * HS_PAD + row] = v.w;
        }
        __syncthreads();

        #pragma unroll 8
        for (int k = 0; k < KC; k++) {
            float4 A = *(const float4*)(hs + k * HS_PAD + r0);
            float4 B = *(const float4*)(hs + k * HS_PAD + r0 + 4);
            float2 hp[4] = { make_float2(A.x, A.y), make_float2(A.z, A.w),
                             make_float2(B.x, B.y), make_float2(B.z, B.w) };
            float4 wv = *(const float4*)(Ws + (kc + k) * WS_PAD + c0);
            float2 w0 = make_float2(wv.x, wv.x);
            float2 w1 = make_float2(wv.y, wv.y);
            float2 w2 = make_float2(wv.z, wv.z);
            float2 w3 = make_float2(wv.w, wv.w);
            #pragma unroll
            for (int p = 0; p < 4; p++) {
                acc[p][0] = ffma2(hp[p], w0, acc[p][0]);
                acc[p][1] = ffma2(hp[p], w1, acc[p][1]);
                acc[p][2] = ffma2(hp[p], w2, acc[p][2]);
                acc[p][3] = ffma2(hp[p], w3, acc[p][3]);
            }
        }
    }

    // Store Wh in fp16 (4 cols per row, 8 rows per thread)
    #pragma unroll
    for (int p = 0; p < 4; p++) {
        int r = R0 + r0 + 2 * p;
        if (r < N_NODES) {
            __half2 h01 = __floats2half2_rn(acc[p][0].x, acc[p][1].x);
            __half2 h23 = __floats2half2_rn(acc[p][2].x, acc[p][3].x);
            uint2 u; u.x = *(unsigned*)&h01; u.y = *(unsigned*)&h23;
            *(uint2*)(g_Whh + (size_t)r * OUT_F + c0) = u;
        }
        if (r + 1 < N_NODES) {
            __half2 h01 = __floats2half2_rn(acc[p][0].y, acc[p][1].y);
            __half2 h23 = __floats2half2_rn(acc[p][2].y, acc[p][3].y);
            uint2 u; u.x = *(unsigned*)&h01; u.y = *(unsigned*)&h23;
            *(uint2*)(g_Whh + (size_t)(r + 1) * OUT_F + c0) = u;
        }
    }

    // Fused s/t projection (fp32 accumulators)
    float2 sp[4], tp[4];
    #pragma unroll
    for (int p = 0; p < 4; p++) { sp[p] = make_float2(0.f, 0.f); tp[p] = make_float2(0.f, 0.f); }
    #pragma unroll
    for (int j = 0; j < 4; j++) {
        float a1v = a[c0 + j];
        float a2v = a[OUT_F + c0 + j];
        float2 a1d = make_float2(a1v, a1v);
        float2 a2d = make_float2(a2v, a2v);
        #pragma unroll
        for (int p = 0; p < 4; p++) {
            sp[p] = ffma2(acc[p][j], a1d, sp[p]);
            tp[p] = ffma2(acc[p][j], a2d, tp[p]);
        }
    }
    #pragma unroll
    for (int o = 8; o > 0; o >>= 1) {
        #pragma unroll
        for (int p = 0; p < 4; p++) {
            sp[p].x += __shfl_down_sync(0xffffffffu, sp[p].x, o, 16);
            sp[p].y += __shfl_down_sync(0xffffffffu, sp[p].y, o, 16);
            tp[p].x += __shfl_down_sync(0xffffffffu, tp[p].x, o, 16);
            tp[p].y += __shfl_down_sync(0xffffffffu, tp[p].y, o, 16);
        }
    }
    if (colg == 0) {
        #pragma unroll
        for (int p = 0; p < 4; p++) {
            int r = R0 + r0 + 2 * p;
            if (r < N_NODES)     { g_s[r]     = sp[p].x; g_t[r]     = tp[p].x; }
            if (r + 1 < N_NODES) { g_s[r + 1] = sp[p].y; g_t[r + 1] = tp[p].y; }
        }
    }
}

// ---------------------------------------------------------------------------
// Kernel 2: process overflow list (normally empty). Runs after gemm done.
// ---------------------------------------------------------------------------
__global__ void ovf_kernel(float* __restrict__ out) {
    int n = g_ovf_cnt; if (n > OVF_MAX) n = OVF_MAX;
    for (int i = blockIdx.x * blockDim.x + threadIdx.x; i < n;
         i += gridDim.x * blockDim.x) {
        int2 e = g_ovf[i];
        float ev = g_s[e.x] + g_t[e.y];
        ev = (ev > 0.0f) ? ev : LRELU_ALPHA * ev;
        float x = fminf(__expf(ev), EXP_CLAMP);
        atomicAdd(g_denom + e.x, x);
        float* o = out + (size_t)e.x * OUT_F;
        const __half* w = g_Whh + (size_t)e.y * OUT_F;
        for (int j = 0; j < OUT_F; j++)
            atomicAdd(o + j, x * __half2float(w[j]));
    }
}

// ---------------------------------------------------------------------------
// Kernel 3 (hot, profiled): one warp per dst node. Lanes batch-compute 32
// x_exp, broadcast (src,x), accumulate sum(x * Whh[src]) in fp32 registers
// (fp16 gather = 128B/row). Normalize + ELU inline.
// ---------------------------------------------------------------------------
__global__ __launch_bounds__(256) void aggregate_kernel(float* __restrict__ out) {
    int warp = (blockIdx.x * blockDim.x + threadIdx.x) >> 5;
    int lane = threadIdx.x & 31;
    if (warp >= N_NODES) return;
    int d = warp;
    int n = g_cnt[d];
    bool ovf = (n > CAP);
    if (ovf) n = CAP;

    float sd = g_s[d];
    const int* bkt = g_bucket + (size_t)d * CAP;

    float2 acc = make_float2(0.f, 0.f);
    float xsum = 0.f;

    for (int base = 0; base < n; base += 32) {
        int i = base + lane;
        int src = 0;
        float x = 0.f;
        if (i < n) {
            src = __ldg(bkt + i);
            float e = sd + __ldg(g_t + src);
            e = (e > 0.0f) ? e : LRELU_ALPHA * e;
            x = fminf(__expf(e), EXP_CLAMP);
            xsum += x;
        }
        int m = n - base; if (m > 32) m = 32;
        #pragma unroll 4
        for (int j = 0; j < m; j++) {
            float xj = __shfl_sync(0xffffffffu, x, j);
            int   sj = __shfl_sync(0xffffffffu, src, j);
            unsigned wv = *(const unsigned*)(g_Whh + (size_t)sj * OUT_F + lane * 2);
            float2 w = __half22float2(*(__half2*)&wv);
            acc = ffma2(make_float2(xj, xj), w, acc);
        }
    }

    #pragma unroll
    for (int o = 16; o > 0; o >>= 1)
        xsum += __shfl_xor_sync(0xffffffffu, xsum, o);

    float2* po = (float2*)(out + (size_t)d * OUT_F) + lane;
    if (!ovf) {
        float r = __frcp_rn(xsum + DENOM_EPS);
        float vx = acc.x * r, vy = acc.y * r;
        vx = (vx > 0.0f) ? vx : expm1f(vx);
        vy = (vy > 0.0f) ? vy : expm1f(vy);
        *po = make_float2(vx, vy);
    } else {
        asm volatile("red.global.add.v2.f32 [%0], {%1, %2};"
                     :: "l"(po), "f"(acc.x), "f"(acc.y) : "memory");
        if (lane == 0) atomicAdd(g_denom + d, xsum);
    }
}

// ---------------------------------------------------------------------------
// Kernel 4: finalize ONLY overflowed nodes (normally none)
// ---------------------------------------------------------------------------
__global__ void final_kernel(float* __restrict__ out) {
    int i = blockIdx.x * blockDim.x + threadIdx.x;
    if (i >= N_NODES * OUT_F) return;
    int d = i >> 6;
    if (g_cnt[d] <= CAP) return;
    float v = out[i] * __frcp_rn(g_denom[d]);
    out[i] = (v > 0.0f) ? v : expm1f(v);
}

// ---------------------------------------------------------------------------
extern "C" void kernel_launch(void* const* d_in, const int* in_sizes, int n_in,
                              void* d_out, int out_size) {
    const float* h   = (const float*)d_in[0];   // [50000, 128]
    const float* W   = (const float*)d_in[1];   // [128, 64]
    const float* a   = (const float*)d_in[2];   // [128, 1]
    const void*  adj = d_in[3];                 // [1.6M, 2] int32 or int64
    float* out = (float*)d_out;                 // [50000, 64]

    const int T = 256;

    static bool smem_set = false;
    if (!smem_set) {
        cudaFuncSetAttribute(gs_kernel,
                             cudaFuncAttributeMaxDynamicSharedMemorySize, GEMM_SMEM);
        smem_set = true;
    }

    {                                                                   // idx 0
        int n = N_NODES * OUT_F / 4;
        init_kernel<<<(n + T - 1) / T, T>>>(out, (const unsigned int*)adj);
    }
    gs_kernel<<<GEMM_BLOCKS + SCAT_BLOCKS, 256, GEMM_SMEM>>>(h, W, a, adj); // idx 1
    ovf_kernel<<<16, 256>>>(out);                                       // idx 2
    {                                                                   // idx 3 (profiled)
        long long threads = (long long)N_NODES * 32;
        int blocks = (int)((threads + T - 1) / T);
        aggregate_kernel<<<blocks, T>>>(out);
    }
    {                                                                   // idx 4
        int total = N_NODES * OUT_F;
        final_kernel<<<(total + T - 1) / T, T>>>(out);
    }
}

// round 9
// speedup vs baseline: 2.9428x; 1.0422x over previous
#include <cuda_runtime.h>
#include <cuda_fp16.h>
#include <cstdint>

#define LRELU_ALPHA 0.2f
#define EXP_CLAMP 1000000.0f
#define DENOM_EPS 1e-10f
#define N_NODES 50000
#define N_EDGES 1600000
#define IN_F 128
#define OUT_F 64
#define CAP 128          // bucket capacity per dst (Poisson(32), max ~70)
#define OVF_MAX 32768

#define TILE_R 128
#define KC 32
#define HS_PAD 132
#define WS_PAD 68
#define GEMM_SMEM ((KC * HS_PAD + IN_F * WS_PAD) * 4)
#define GEMM_BLOCKS ((N_NODES + TILE_R - 1) / TILE_R)        // 391
#define SCAT_BLOCKS ((N_EDGES + 255) / 256)                  // 6250

// Device scratch (no allocation allowed in kernel_launch)
__device__ __half g_Whh[N_NODES * OUT_F];     // fp16 Wh (6.4 MB)
__device__ float g_s[N_NODES];
__device__ float g_t[N_NODES];
__device__ float g_denom[N_NODES];
__device__ int   g_cnt[N_NODES];
__device__ int   g_bucket[N_NODES * CAP];     // 25.6 MB
__device__ int   g_ovf_cnt;
__device__ int2  g_ovf[OVF_MAX];
__device__ int   g_adj64;

// Packed fp32x2 FMA (Blackwell sm_100+)
__device__ __forceinline__ float2 ffma2(float2 a, float2 b, float2 c) {
    float2 d;
    asm("fma.rn.f32x2 %0, %1, %2, %3;"
        : "=l"(*(unsigned long long*)&d)
        : "l"(*(unsigned long long*)&a),
          "l"(*(unsigned long long*)&b),
          "l"(*(unsigned long long*)&c));
    return d;
}

__device__ __forceinline__ void load_edge(const void* __restrict__ adj, int i,
                                          int& dst, int& src) {
    if (g_adj64) {
        const longlong2* p = (const longlong2*)adj;
        longlong2 v = __ldg(p + i);
        dst = (int)v.x; src = (int)v.y;
    } else {
        const int2* p = (const int2*)adj;
        int2 v = __ldg(p + i);
        dst = v.x; src = v.y;
    }
}

// ---------------------------------------------------------------------------
// Kernel 0: init (denom=eps, cnt=0, ovf_cnt=0) + fused adj dtype detect.
// NOTE: out is NOT zeroed — aggregate overwrites every row; overflowed rows
// (never in practice) are zeroed lazily by the scatter thread seeing c==CAP.
// ---------------------------------------------------------------------------
__global__ void init_kernel(const unsigned int* __restrict__ adj_raw) {
    int i = blockIdx.x * blockDim.x + threadIdx.x;
    if (i < N_NODES) { g_denom[i] = DENOM_EPS; g_cnt[i] = 0; }
    if (i == 0) g_ovf_cnt = 0;

    if (blockIdx.x == 0 && threadIdx.x < 32) {
        unsigned int acc = 0;
        for (int j = 1 + 2 * threadIdx.x; j < 8192; j += 64)
            acc |= adj_raw[j];
        #pragma unroll
        for (int o = 16; o > 0; o >>= 1)
            acc |= __shfl_down_sync(0xffffffffu, acc, o);
        if (threadIdx.x == 0) g_adj64 = (acc == 0) ? 1 : 0;
    }
}

// ---------------------------------------------------------------------------
// Kernel 1 (fused): blocks [0,391) do GEMM tile; blocks [391, 6641) do the
// bucket scatter. The two halves are fully independent.
// ---------------------------------------------------------------------------
__global__ __launch_bounds__(256) void gs_kernel(const float* __restrict__ h,
                                                 const float* __restrict__ W,
                                                 const float* __restrict__ a,
                                                 const void* __restrict__ adj,
                                                 float* __restrict__ out) {
    if (blockIdx.x >= GEMM_BLOCKS) {
        // ---- scatter: bin src by dst; overflow goes to explicit list ----
        int i = (blockIdx.x - GEMM_BLOCKS) * 256 + threadIdx.x;
        if (i >= N_EDGES) return;
        int dst, src;
        load_edge(adj, i, dst, src);
        int c = atomicAdd(g_cnt + dst, 1);
        if (c < CAP) {
            g_bucket[(size_t)dst * CAP + c] = src;
        } else {
            if (c == CAP) {
                // first overflow for this node: zero its output row (exactly
                // one thread; ordered before ovf/aggregate by launch bounds)
                float4 z = make_float4(0.f, 0.f, 0.f, 0.f);
                float4* o = (float4*)(out + (size_t)dst * OUT_F);
                #pragma unroll
                for (int j = 0; j < OUT_F / 4; j++) o[j] = z;
            }
            int p = atomicAdd(&g_ovf_cnt, 1);
            if (p < OVF_MAX) g_ovf[p] = make_int2(dst, src);
        }
        return;
    }

    // ---- GEMM: Wh = h @ W (fp16 out) with fused s/t projection ----
    extern __shared__ float smem[];
    float* hs = smem;                         // [KC][HS_PAD] transposed h chunk
    float* Ws = smem + KC * HS_PAD;           // [IN_F][WS_PAD]

    int tid = threadIdx.x;
    for (int i = tid; i < IN_F * OUT_F; i += 256) {
        int k = i >> 6, c = i & 63;
        Ws[k * WS_PAD + c] = W[i];
    }

    int colg = tid & 15;
    int rowg = tid >> 4;
    int c0 = colg * 4;
    int r0 = rowg * 8;
    int R0 = blockIdx.x * TILE_R;

    float2 acc[4][4];
    #pragma unroll
    for (int p = 0; p < 4; p++)
        #pragma unroll
        for (int j = 0; j < 4; j++)
            acc[p][j] = make_float2(0.f, 0.f);

    for (int kc = 0; kc < IN_F; kc += KC) {
        __syncthreads();
        #pragma unroll
        for (int it = 0; it < (TILE_R * KC / 4) / 256; it++) {
            int i   = tid + it * 256;
            int row = i >> 3;
            int k4  = i & 7;
            int gr  = R0 + row;
            if (gr >= N_NODES) gr = 0;
            float4 v = *(const float4*)(h + (size_t)gr * IN_F + kc + k4 * 4);
            hs[(k4 * 4 + 0) * HS_PAD + row] = v.x;
            hs[(k4 * 4 + 1) * HS_PAD + row] = v.y;
            hs[(k4 * 4 + 2) * HS_PAD + row] = v.z;
            hs[(k4 * 4 + 3) * HS_PAD + row] = v.w;
        }
        __syncthreads();

        #pragma unroll 8
        for (int k = 0; k < KC; k++) {
            float4 A = *(const float4*)(hs + k * HS_PAD + r0);
            float4 B = *(const float4*)(hs + k * HS_PAD + r0 + 4);
            float2 hp[4] = { make_float2(A.x, A.y), make_float2(A.z, A.w),
                             make_float2(B.x, B.y), make_float2(B.z, B.w) };
            float4 wv = *(const float4*)(Ws + (kc + k) * WS_PAD + c0);
            float2 w0 = make_float2(wv.x, wv.x);
            float2 w1 = make_float2(wv.y, wv.y);
            float2 w2 = make_float2(wv.z, wv.z);
            float2 w3 = make_float2(wv.w, wv.w);
            #pragma unroll
            for (int p = 0; p < 4; p++) {
                acc[p][0] = ffma2(hp[p], w0, acc[p][0]);
                acc[p][1] = ffma2(hp[p], w1, acc[p][1]);
                acc[p][2] = ffma2(hp[p], w2, acc[p][2]);
                acc[p][3] = ffma2(hp[p], w3, acc[p][3]);
            }
        }
    }

    // Store Wh in fp16 (4 cols per row, 8 rows per thread)
    #pragma unroll
    for (int p = 0; p < 4; p++) {
        int r = R0 + r0 + 2 * p;
        if (r < N_NODES) {
            __half2 h01 = __floats2half2_rn(acc[p][0].x, acc[p][1].x);
            __half2 h23 = __floats2half2_rn(acc[p][2].x, acc[p][3].x);
            uint2 u; u.x = *(unsigned*)&h01; u.y = *(unsigned*)&h23;
            *(uint2*)(g_Whh + (size_t)r * OUT_F + c0) = u;
        }
        if (r + 1 < N_NODES) {
            __half2 h01 = __floats2half2_rn(acc[p][0].y, acc[p][1].y);
            __half2 h23 = __floats2half2_rn(acc[p][2].y, acc[p][3].y);
            uint2 u; u.x = *(unsigned*)&h01; u.y = *(unsigned*)&h23;
            *(uint2*)(g_Whh + (size_t)(r + 1) * OUT_F + c0) = u;
        }
    }

    // Fused s/t projection (fp32 accumulators)
    float2 sp[4], tp[4];
    #pragma unroll
    for (int p = 0; p < 4; p++) { sp[p] = make_float2(0.f, 0.f); tp[p] = make_float2(0.f, 0.f); }
    #pragma unroll
    for (int j = 0; j < 4; j++) {
        float a1v = a[c0 + j];
        float a2v = a[OUT_F + c0 + j];
        float2 a1d = make_float2(a1v, a1v);
        float2 a2d = make_float2(a2v, a2v);
        #pragma unroll
        for (int p = 0; p < 4; p++) {
            sp[p] = ffma2(acc[p][j], a1d, sp[p]);
            tp[p] = ffma2(acc[p][j], a2d, tp[p]);
        }
    }
    #pragma unroll
    for (int o = 8; o > 0; o >>= 1) {
        #pragma unroll
        for (int p = 0; p < 4; p++) {
            sp[p].x += __shfl_down_sync(0xffffffffu, sp[p].x, o, 16);
            sp[p].y += __shfl_down_sync(0xffffffffu, sp[p].y, o, 16);
            tp[p].x += __shfl_down_sync(0xffffffffu, tp[p].x, o, 16);
            tp[p].y += __shfl_down_sync(0xffffffffu, tp[p].y, o, 16);
        }
    }
    if (colg == 0) {
        #pragma unroll
        for (int p = 0; p < 4; p++) {
            int r = R0 + r0 + 2 * p;
            if (r < N_NODES)     { g_s[r]     = sp[p].x; g_t[r]     = tp[p].x; }
            if (r + 1 < N_NODES) { g_s[r + 1] = sp[p].y; g_t[r + 1] = tp[p].y; }
        }
    }
}

// ---------------------------------------------------------------------------
// Kernel 2: process overflow list (normally empty). Runs after gs done.
// ---------------------------------------------------------------------------
__global__ void ovf_kernel(float* __restrict__ out) {
    int n = g_ovf_cnt; if (n > OVF_MAX) n = OVF_MAX;
    for (int i = blockIdx.x * blockDim.x + threadIdx.x; i < n;
         i += gridDim.x * blockDim.x) {
        int2 e = g_ovf[i];
        float ev = g_s[e.x] + g_t[e.y];
        ev = (ev > 0.0f) ? ev : LRELU_ALPHA * ev;
        float x = fminf(__expf(ev), EXP_CLAMP);
        atomicAdd(g_denom + e.x, x);
        float* o = out + (size_t)e.x * OUT_F;
        const __half* w = g_Whh + (size_t)e.y * OUT_F;
        for (int j = 0; j < OUT_F; j++)
            atomicAdd(o + j, x * __half2float(w[j]));
    }
}

// ---------------------------------------------------------------------------
// Kernel 3 (hot, profiled): one warp per dst node.
// Phase A: lanes batch-compute 32 x_exp + precomputed byte offsets, staged
// to smem (replaces 2 shfl/edge with 1 LDS.64 broadcast).
// Phase B: gather fp16 rows, accumulate fp32 in DUAL accumulators (halved
// FFMA dependency chain). Normalize + ELU inline, single coalesced store.
// ---------------------------------------------------------------------------
__global__ __launch_bounds__(256) void aggregate_kernel(float* __restrict__ out) {
    __shared__ float2 stage_s[8][32];
    int wl   = threadIdx.x >> 5;
    int warp = (blockIdx.x * blockDim.x + threadIdx.x) >> 5;
    int lane = threadIdx.x & 31;
    if (warp >= N_NODES) return;
    int d = warp;
    int n = g_cnt[d];
    bool ovf = (n > CAP);
    if (ovf) n = CAP;

    float sd = g_s[d];
    const int* bkt = g_bucket + (size_t)d * CAP;
    const char* whbase = (const char*)g_Whh + lane * 4;   // lane's half2 column
    float2* stg = stage_s[wl];

    float2 acc0 = make_float2(0.f, 0.f);
    float2 acc1 = make_float2(0.f, 0.f);
    float xsum = 0.f;

    for (int base = 0; base < n; base += 32) {
        int i = base + lane;
        float x = 0.f;
        int off = 0;                           // row 0, x=0 => harmless pad
        if (i < n) {
            int src = __ldg(bkt + i);
            float e = sd + __ldg(g_t + src);
            e = (e > 0.0f) ? e : LRELU_ALPHA * e;
            x = fminf(__expf(e), EXP_CLAMP);
            xsum += x;
            off = src << 7;                    // src * 128 bytes (fp16 row)
        }
        stg[lane] = make_float2(x, __int_as_float(off));
        __syncwarp();

        int m = n - base; if (m > 32) m = 32;
        int mm = (m + 1) & ~1;                 // padded entries are x=0
        #pragma unroll 4
        for (int j = 0; j < mm; j += 2) {
            float2 p0 = stg[j];
            float2 p1 = stg[j + 1];
            unsigned wv0 = *(const unsigned*)(whbase + __float_as_int(p0.y));
            unsigned wv1 = *(const unsigned*)(whbase + __float_as_int(p1.y));
            float2 w0 = __half22float2(*(__half2*)&wv0);
            float2 w1 = __half22float2(*(__half2*)&wv1);
            acc0 = ffma2(make_float2(p0.x, p0.x), w0, acc0);
            acc1 = ffma2(make_float2(p1.x, p1.x), w1, acc1);
        }
        __syncwarp();
    }

    float2 acc = make_float2(acc0.x + acc1.x, acc0.y + acc1.y);

    #pragma unroll
    for (int o = 16; o > 0; o >>= 1)
        xsum += __shfl_xor_sync(0xffffffffu, xsum, o);

    float2* po = (float2*)(out + (size_t)d * OUT_F) + lane;
    if (!ovf) {
        float r = __frcp_rn(xsum + DENOM_EPS);
        float vx = acc.x * r, vy = acc.y * r;
        vx = (vx > 0.0f) ? vx : expm1f(vx);
        vy = (vy > 0.0f) ? vy : expm1f(vy);
        *po = make_float2(vx, vy);
    } else {
        asm volatile("red.global.add.v2.f32 [%0], {%1, %2};"
                     :: "l"(po), "f"(acc.x), "f"(acc.y) : "memory");
        if (lane == 0) atomicAdd(g_denom + d, xsum);
    }
}

// ---------------------------------------------------------------------------
// Kernel 4: finalize ONLY overflowed nodes (normally none; uniform early-out)
// ---------------------------------------------------------------------------
__global__ void final_kernel(float* __restrict__ out) {
    if (g_ovf_cnt == 0) return;
    int i = blockIdx.x * blockDim.x + threadIdx.x;
    if (i >= N_NODES * OUT_F) return;
    int d = i >> 6;
    if (g_cnt[d] <= CAP) return;
    float v = out[i] * __frcp_rn(g_denom[d]);
    out[i] = (v > 0.0f) ? v : expm1f(v);
}

// ---------------------------------------------------------------------------
extern "C" void kernel_launch(void* const* d_in, const int* in_sizes, int n_in,
                              void* d_out, int out_size) {
    const float* h   = (const float*)d_in[0];   // [50000, 128]
    const float* W   = (const float*)d_in[1];   // [128, 64]
    const float* a   = (const float*)d_in[2];   // [128, 1]
    const void*  adj = d_in[3];                 // [1.6M, 2] int32 or int64
    float* out = (float*)d_out;                 // [50000, 64]

    const int T = 256;

    static bool smem_set = false;
    if (!smem_set) {
        cudaFuncSetAttribute(gs_kernel,
                             cudaFuncAttributeMaxDynamicSharedMemorySize, GEMM_SMEM);
        smem_set = true;
    }

    init_kernel<<<(N_NODES + T - 1) / T, T>>>((const unsigned int*)adj);     // idx 0
    gs_kernel<<<GEMM_BLOCKS + SCAT_BLOCKS, 256, GEMM_SMEM>>>(h, W, a, adj, out); // idx 1
    ovf_kernel<<<16, 256>>>(out);                                            // idx 2
    {                                                                        // idx 3 (profiled)
        long long threads = (long long)N_NODES * 32;
        int blocks = (int)((threads + T - 1) / T);
        aggregate_kernel<<<blocks, T>>>(out);
    }
    {                                                                        // idx 4
        int total = N_NODES * OUT_F;
        final_kernel<<<(total + T - 1) / T, T>>>(out);
    }
}

// round 10
// speedup vs baseline: 3.4150x; 1.1604x over previous
#include <cuda_runtime.h>
#include <cuda_fp16.h>
#include <cstdint>

#define LRELU_ALPHA 0.2f
#define EXP_CLAMP 1000000.0f
#define DENOM_EPS 1e-10f
#define N_NODES 50000
#define N_EDGES 1600000
#define IN_F 128
#define OUT_F 64
#define CAP 128          // bucket capacity per dst (Poisson(32), max ~70)
#define OVF_MAX 32768

#define TILE_R 128
#define KC 32
#define HS_PAD 132
#define WS_PAD 68
#define GEMM_SMEM ((KC * HS_PAD + IN_F * WS_PAD) * 4)
#define GEMM_BLOCKS ((N_NODES + TILE_R - 1) / TILE_R)        // 391
#define SCAT_BLOCKS ((N_EDGES + 255) / 256)                  // 6250
#define AGG_BLOCKS  ((N_NODES * 32 + 255) / 256)             // 6250
#define OVF_BLOCKS  16

// Device scratch (no allocation allowed in kernel_launch)
__device__ __half g_Whh[N_NODES * OUT_F];     // fp16 Wh (6.4 MB)
__device__ float g_s[N_NODES];
__device__ float g_t[N_NODES];
__device__ float g_denom[N_NODES];
__device__ int   g_cnt[N_NODES];
__device__ int   g_bucket[N_NODES * CAP];     // 25.6 MB
__device__ int   g_ovf_cnt;
__device__ int2  g_ovf[OVF_MAX];
__device__ int   g_adj64;

// Packed fp32x2 FMA (Blackwell sm_100+)
__device__ __forceinline__ float2 ffma2(float2 a, float2 b, float2 c) {
    float2 d;
    asm("fma.rn.f32x2 %0, %1, %2, %3;"
        : "=l"(*(unsigned long long*)&d)
        : "l"(*(unsigned long long*)&a),
          "l"(*(unsigned long long*)&b),
          "l"(*(unsigned long long*)&c));
    return d;
}

__device__ __forceinline__ void load_edge(const void* __restrict__ adj, int i,
                                          int& dst, int& src) {
    if (g_adj64) {
        const longlong2* p = (const longlong2*)adj;
        longlong2 v = __ldg(p + i);
        dst = (int)v.x; src = (int)v.y;
    } else {
        const int2* p = (const int2*)adj;
        int2 v = __ldg(p + i);
        dst = v.x; src = v.y;
    }
}

// ---------------------------------------------------------------------------
// Kernel 0: init (denom=eps, cnt=0, ovf_cnt=0) + fused adj dtype detect.
// out is NOT zeroed — aggregate overwrites every non-overflow row.
// ---------------------------------------------------------------------------
__global__ void init_kernel(const unsigned int* __restrict__ adj_raw) {
    int i = blockIdx.x * blockDim.x + threadIdx.x;
    if (i < N_NODES) { g_denom[i] = DENOM_EPS; g_cnt[i] = 0; }
    if (i == 0) g_ovf_cnt = 0;

    if (blockIdx.x == 0 && threadIdx.x < 32) {
        unsigned int acc = 0;
        for (int j = 1 + 2 * threadIdx.x; j < 8192; j += 64)
            acc |= adj_raw[j];
        #pragma unroll
        for (int o = 16; o > 0; o >>= 1)
            acc |= __shfl_down_sync(0xffffffffu, acc, o);
        if (threadIdx.x == 0) g_adj64 = (acc == 0) ? 1 : 0;
    }
}

// ---------------------------------------------------------------------------
// Kernel 1 (fused): blocks [0,391) GEMM; blocks [391, 6641) bucket scatter.
// ---------------------------------------------------------------------------
__global__ __launch_bounds__(256) void gs_kernel(const float* __restrict__ h,
                                                 const float* __restrict__ W,
                                                 const float* __restrict__ a,
                                                 const void* __restrict__ adj,
                                                 float* __restrict__ out) {
    if (blockIdx.x >= GEMM_BLOCKS) {
        // ---- scatter: bin src by dst; overflow goes to explicit list ----
        int i = (blockIdx.x - GEMM_BLOCKS) * 256 + threadIdx.x;
        if (i >= N_EDGES) return;
        int dst, src;
        load_edge(adj, i, dst, src);
        int c = atomicAdd(g_cnt + dst, 1);
        if (c < CAP) {
            g_bucket[(size_t)dst * CAP + c] = src;
        } else {
            if (c == CAP) {
                // first overflow: zero this node's output row (exactly once)
                float4 z = make_float4(0.f, 0.f, 0.f, 0.f);
                float4* o = (float4*)(out + (size_t)dst * OUT_F);
                #pragma unroll
                for (int j = 0; j < OUT_F / 4; j++) o[j] = z;
            }
            int p = atomicAdd(&g_ovf_cnt, 1);
            if (p < OVF_MAX) g_ovf[p] = make_int2(dst, src);
        }
        return;
    }

    // ---- GEMM: Wh = h @ W (fp16 out) with fused s/t projection ----
    extern __shared__ float smem[];
    float* hs = smem;                         // [KC][HS_PAD] transposed h chunk
    float* Ws = smem + KC * HS_PAD;           // [IN_F][WS_PAD]

    int tid = threadIdx.x;
    for (int i = tid; i < IN_F * OUT_F; i += 256) {
        int k = i >> 6, c = i & 63;
        Ws[k * WS_PAD + c] = W[i];
    }

    int colg = tid & 15;
    int rowg = tid >> 4;
    int c0 = colg * 4;
    int r0 = rowg * 8;
    int R0 = blockIdx.x * TILE_R;

    float2 acc[4][4];
    #pragma unroll
    for (int p = 0; p < 4; p++)
        #pragma unroll
        for (int j = 0; j < 4; j++)
            acc[p][j] = make_float2(0.f, 0.f);

    for (int kc = 0; kc < IN_F; kc += KC) {
        __syncthreads();
        #pragma unroll
        for (int it = 0; it < (TILE_R * KC / 4) / 256; it++) {
            int i   = tid + it * 256;
            int row = i >> 3;
            int k4  = i & 7;
            int gr  = R0 + row;
            if (gr >= N_NODES) gr = 0;
            float4 v = *(const float4*)(h + (size_t)gr * IN_F + kc + k4 * 4);
            hs[(k4 * 4 + 0) * HS_PAD + row] = v.x;
            hs[(k4 * 4 + 1) * HS_PAD + row] = v.y;
            hs[(k4 * 4 + 2) * HS_PAD + row] = v.z;
            hs[(k4 * 4 + 3) * HS_PAD + row] = v.w;
        }
        __syncthreads();

        #pragma unroll 8
        for (int k = 0; k < KC; k++) {
            float4 A = *(const float4*)(hs + k * HS_PAD + r0);
            float4 B = *(const float4*)(hs + k * HS_PAD + r0 + 4);
            float2 hp[4] = { make_float2(A.x, A.y), make_float2(A.z, A.w),
                             make_float2(B.x, B.y), make_float2(B.z, B.w) };
            float4 wv = *(const float4*)(Ws + (kc + k) * WS_PAD + c0);
            float2 w0 = make_float2(wv.x, wv.x);
            float2 w1 = make_float2(wv.y, wv.y);
            float2 w2 = make_float2(wv.z, wv.z);
            float2 w3 = make_float2(wv.w, wv.w);
            #pragma unroll
            for (int p = 0; p < 4; p++) {
                acc[p][0] = ffma2(hp[p], w0, acc[p][0]);
                acc[p][1] = ffma2(hp[p], w1, acc[p][1]);
                acc[p][2] = ffma2(hp[p], w2, acc[p][2]);
                acc[p][3] = ffma2(hp[p], w3, acc[p][3]);
            }
        }
    }

    #pragma unroll
    for (int p = 0; p < 4; p++) {
        int r = R0 + r0 + 2 * p;
        if (r < N_NODES) {
            __half2 h01 = __floats2half2_rn(acc[p][0].x, acc[p][1].x);
            __half2 h23 = __floats2half2_rn(acc[p][2].x, acc[p][3].x);
            uint2 u; u.x = *(unsigned*)&h01; u.y = *(unsigned*)&h23;
            *(uint2*)(g_Whh + (size_t)r * OUT_F + c0) = u;
        }
        if (r + 1 < N_NODES) {
            __half2 h01 = __floats2half2_rn(acc[p][0].y, acc[p][1].y);
            __half2 h23 = __floats2half2_rn(acc[p][2].y, acc[p][3].y);
            uint2 u; u.x = *(unsigned*)&h01; u.y = *(unsigned*)&h23;
            *(uint2*)(g_Whh + (size_t)(r + 1) * OUT_F + c0) = u;
        }
    }

    float2 sp[4], tp[4];
    #pragma unroll
    for (int p = 0; p < 4; p++) { sp[p] = make_float2(0.f, 0.f); tp[p] = make_float2(0.f, 0.f); }
    #pragma unroll
    for (int j = 0; j < 4; j++) {
        float a1v = a[c0 + j];
        float a2v = a[OUT_F + c0 + j];
        float2 a1d = make_float2(a1v, a1v);
        float2 a2d = make_float2(a2v, a2v);
        #pragma unroll
        for (int p = 0; p < 4; p++) {
            sp[p] = ffma2(acc[p][j], a1d, sp[p]);
            tp[p] = ffma2(acc[p][j], a2d, tp[p]);
        }
    }
    #pragma unroll
    for (int o = 8; o > 0; o >>= 1) {
        #pragma unroll
        for (int p = 0; p < 4; p++) {
            sp[p].x += __shfl_down_sync(0xffffffffu, sp[p].x, o, 16);
            sp[p].y += __shfl_down_sync(0xffffffffu, sp[p].y, o, 16);
            tp[p].x += __shfl_down_sync(0xffffffffu, tp[p].x, o, 16);
            tp[p].y += __shfl_down_sync(0xffffffffu, tp[p].y, o, 16);
        }
    }
    if (colg == 0) {
        #pragma unroll
        for (int p = 0; p < 4; p++) {
            int r = R0 + r0 + 2 * p;
            if (r < N_NODES)     { g_s[r]     = sp[p].x; g_t[r]     = tp[p].x; }
            if (r + 1 < N_NODES) { g_s[r + 1] = sp[p].y; g_t[r + 1] = tp[p].y; }
        }
    }
}

// ---------------------------------------------------------------------------
// Kernel 2 (hot): one warp per dst node; ovf blocks appended at tail.
// Phase A: lanes batch-compute 32 x_exp + byte offsets -> smem stage.
// Phase B: HALF-WARP per edge — lanes 0-15 edge j, lanes 16-31 edge j+1.
// Each lane owns 4 output cols (LDG.64 of 4 halves). Dual float2 accs.
// Epilogue folds odd-edge half into lanes 0-15, normalize+ELU, float4 store.
// ---------------------------------------------------------------------------
__global__ __launch_bounds__(256) void aggregate_kernel(float* __restrict__ out) {
    if (blockIdx.x >= AGG_BLOCKS) {
        // ---- overflow list processing (normally empty) ----
        int n = g_ovf_cnt; if (n > OVF_MAX) n = OVF_MAX;
        for (int i = (blockIdx.x - AGG_BLOCKS) * 256 + threadIdx.x; i < n;
             i += OVF_BLOCKS * 256) {
            int2 e = g_ovf[i];
            float ev = g_s[e.x] + g_t[e.y];
            ev = (ev > 0.0f) ? ev : LRELU_ALPHA * ev;
            float x = fminf(__expf(ev), EXP_CLAMP);
            atomicAdd(g_denom + e.x, x);
            float* o = out + (size_t)e.x * OUT_F;
            const __half* w = g_Whh + (size_t)e.y * OUT_F;
            for (int j = 0; j < OUT_F; j++)
                atomicAdd(o + j, x * __half2float(w[j]));
        }
        return;
    }

    __shared__ float2 stage_s[8][32];
    int wl   = threadIdx.x >> 5;
    int warp = (blockIdx.x * blockDim.x + threadIdx.x) >> 5;
    int lane = threadIdx.x & 31;
    if (warp >= N_NODES) return;
    int d = warp;
    int n = g_cnt[d];
    bool ovf = (n > CAP);
    if (ovf) n = CAP;

    int half    = lane >> 4;            // 0: even edges, 1: odd edges
    int sublane = lane & 15;            // owns cols [4*sublane, 4*sublane+4)

    float sd = g_s[d];
    const int* bkt = g_bucket + (size_t)d * CAP;
    const char* whbase = (const char*)g_Whh + sublane * 8;
    float2* stg = stage_s[wl];

    float2 acc0 = make_float2(0.f, 0.f);   // cols 4s+0,4s+1
    float2 acc1 = make_float2(0.f, 0.f);   // cols 4s+2,4s+3
    float xsum = 0.f;

    for (int base = 0; base < n; base += 32) {
        int i = base + lane;
        float x = 0.f;
        int off = 0;                       // pad: row 0, x=0 -> harmless
        if (i < n) {
            int src = __ldg(bkt + i);
            float e = sd + __ldg(g_t + src);
            e = (e > 0.0f) ? e : LRELU_ALPHA * e;
            x = fminf(__expf(e), EXP_CLAMP);
            xsum += x;
            off = src << 7;                // src * 128 bytes (fp16 row)
        }
        stg[lane] = make_float2(x, __int_as_float(off));
        __syncwarp();

        int m = n - base; if (m > 32) m = 32;
        int mm = (m + 1) & ~1;             // padded entries have x=0
        #pragma unroll 4
        for (int j = half; j < mm; j += 2) {
            float2 p = stg[j];
            uint2 wv = *(const uint2*)(whbase + __float_as_int(p.y));
            float2 w0 = __half22float2(*(__half2*)&wv.x);
            float2 w1 = __half22float2(*(__half2*)&wv.y);
            float2 xx = make_float2(p.x, p.x);
            acc0 = ffma2(xx, w0, acc0);
            acc1 = ffma2(xx, w1, acc1);
        }
        __syncwarp();
    }

    // fold odd-edge half-warp into lanes 0-15
    acc0.x += __shfl_down_sync(0xffffffffu, acc0.x, 16);
    acc0.y += __shfl_down_sync(0xffffffffu, acc0.y, 16);
    acc1.x += __shfl_down_sync(0xffffffffu, acc1.x, 16);
    acc1.y += __shfl_down_sync(0xffffffffu, acc1.y, 16);

    #pragma unroll
    for (int o = 16; o > 0; o >>= 1)
        xsum += __shfl_xor_sync(0xffffffffu, xsum, o);

    if (half == 0) {
        float4* po = (float4*)(out + (size_t)d * OUT_F) + sublane;
        if (!ovf) {
            float r = __frcp_rn(xsum + DENOM_EPS);
            float v0 = acc0.x * r, v1 = acc0.y * r;
            float v2 = acc1.x * r, v3 = acc1.y * r;
            v0 = (v0 > 0.0f) ? v0 : expm1f(v0);
            v1 = (v1 > 0.0f) ? v1 : expm1f(v1);
            v2 = (v2 > 0.0f) ? v2 : expm1f(v2);
            v3 = (v3 > 0.0f) ? v3 : expm1f(v3);
            *po = make_float4(v0, v1, v2, v3);
        } else {
            asm volatile("red.global.add.v4.f32 [%0], {%1, %2, %3, %4};"
                         :: "l"(po), "f"(acc0.x), "f"(acc0.y),
                            "f"(acc1.x), "f"(acc1.y) : "memory");
            if (sublane == 0) atomicAdd(g_denom + d, xsum);
        }
    }
}

// ---------------------------------------------------------------------------
// Kernel 3: finalize ONLY overflowed nodes (normally none; grid-stride)
// ---------------------------------------------------------------------------
__global__ void final_kernel(float* __restrict__ out) {
    if (g_ovf_cnt == 0) return;
    for (int i = blockIdx.x * blockDim.x + threadIdx.x; i < N_NODES * OUT_F;
         i += gridDim.x * blockDim.x) {
        int d = i >> 6;
        if (g_cnt[d] <= CAP) continue;
        float v = out[i] * __frcp_rn(g_denom[d]);
        out[i] = (v > 0.0f) ? v : expm1f(v);
    }
}

// ---------------------------------------------------------------------------
extern "C" void kernel_launch(void* const* d_in, const int* in_sizes, int n_in,
                              void* d_out, int out_size) {
    const float* h   = (const float*)d_in[0];   // [50000, 128]
    const float* W   = (const float*)d_in[1];   // [128, 64]
    const float* a   = (const float*)d_in[2];   // [128, 1]
    const void*  adj = d_in[3];                 // [1.6M, 2] int32 or int64
    float* out = (float*)d_out;                 // [50000, 64]

    const int T = 256;

    static bool smem_set = false;
    if (!smem_set) {
        cudaFuncSetAttribute(gs_kernel,
                             cudaFuncAttributeMaxDynamicSharedMemorySize, GEMM_SMEM);
        smem_set = true;
    }

    init_kernel<<<(N_NODES + T - 1) / T, T>>>((const unsigned int*)adj);        // idx 0
    gs_kernel<<<GEMM_BLOCKS + SCAT_BLOCKS, 256, GEMM_SMEM>>>(h, W, a, adj, out);// idx 1
    aggregate_kernel<<<AGG_BLOCKS + OVF_BLOCKS, T>>>(out);                      // idx 2
    final_kernel<<<256, T>>>(out);                                              // idx 3
}